// round 14
// baseline (speedup 1.0000x reference)
#include <cuda_runtime.h>
#include <cuda_bf16.h>

#define N_NODES 50000
#define N_EDGES 500000
#define HID 128
#define NUM_GRAPHS 64
#define SLOT 64

typedef unsigned long long u64;
typedef unsigned int u32;

__device__ __forceinline__ u64 pk2(float lo, float hi) {
    u64 r; asm("mov.b64 %0, {%1,%2};" : "=l"(r) : "f"(lo), "f"(hi)); return r;
}
__device__ __forceinline__ void upk2(float& lo, float& hi, u64 v) {
    asm("mov.b64 {%0,%1}, %2;" : "=f"(lo), "=f"(hi) : "l"(v));
}
__device__ __forceinline__ u64 fma2(u64 a, u64 b, u64 c) {
    u64 d; asm("fma.rn.f32x2 %0, %1, %2, %3;" : "=l"(d) : "l"(a), "l"(b), "l"(c)); return d;
}
__device__ __forceinline__ u64 add2(u64 a, u64 b) {
    u64 d; asm("add.rn.f32x2 %0, %1, %2;" : "=l"(d) : "l"(a), "l"(b)); return d;
}
__device__ __forceinline__ u32 to_tf32(float f) {
    u32 r; asm("cvt.rna.tf32.f32 %0, %1;" : "=r"(r) : "f"(f)); return r;
}

// ---------------- scratch (device globals) ------------------------------------
__device__ __align__(16) float g_ar[N_NODES * HID];
__device__ __align__(16) float g_ac[N_NODES * HID];
__device__ __align__(16) float g_au[N_NODES * HID];
__device__ __align__(16) float g_agg[N_NODES * HID];
__device__ __align__(16) float g_gsum[NUM_GRAPHS * HID];
__device__ float g_gcnt[NUM_GRAPHS];

__device__ int g_cursor[N_NODES];
__device__ __align__(8) int2 g_slot[N_NODES * SLOT];

// folded weights
__device__ __align__(16) float g_A[16 * HID];
__device__ __align__(16) float g_B[16 * HID];
__device__ __align__(16) float g_C[16 * HID];
__device__ __align__(16) float g_We2[8 * HID];
__device__ float g_bmsg[HID];
__device__ float g_bu2[HID];

// ---------------- kernel 1: zero + fold (fused) --------------------------------
__global__ void __launch_bounds__(256) init_kernel(
        const float* __restrict__ Wn, const float* __restrict__ bn,
        const float* __restrict__ We, const float* __restrict__ be,
        const float* __restrict__ Wm, const float* __restrict__ bm,
        const float* __restrict__ Wu, const float* __restrict__ bu) {
    int b = blockIdx.x;
    int tid = threadIdx.x;
    if (b >= 25) {
        int nz = gridDim.x - 25;
        int i = (b - 25) * 256 + tid;
        int stride = nz * 256;
        for (int k = i; k < N_NODES; k += stride) g_cursor[k] = 0;
        for (int k = i; k < NUM_GRAPHS * HID; k += stride) g_gsum[k] = 0.f;
        for (int k = i; k < NUM_GRAPHS; k += stride) g_gcnt[k] = 0.f;
        return;
    }
    if (tid >= 128) return;
    int j = tid;
    if (b < 16) {
        int i = b;
        float sa = 0.f, sb = 0.f, sc = 0.f;
        for (int k = 0; k < 128; k++) {
            float w = __ldg(Wn + i * 128 + k);
            sa += w * __ldg(Wm + k * 128 + j);
            sb += w * __ldg(Wm + (128 + k) * 128 + j);
            sc += w * __ldg(Wu + k * 128 + j);
        }
        g_A[i * 128 + j] = sa;
        g_B[i * 128 + j] = sb;
        g_C[i * 128 + j] = sc;
    } else if (b < 24) {
        int i = b - 16;
        float s = 0.f;
        for (int k = 0; k < 128; k++)
            s += __ldg(We + i * 128 + k) * __ldg(Wm + (256 + k) * 128 + j);
        g_We2[i * 128 + j] = s;
    } else {
        float bmsg = bm[j];
        float bu2 = bu[j];
        for (int k = 0; k < 128; k++) {
            bmsg += bn[k] * (__ldg(Wm + k * 128 + j) + __ldg(Wm + (128 + k) * 128 + j));
            bmsg += be[k] * __ldg(Wm + (256 + k) * 128 + j);
            bu2 += bn[k] * __ldg(Wu + k * 128 + j);
        }
        g_bmsg[j] = bmsg;
        g_bu2[j] = bu2;
    }
}

// ---------------- kernel 2: node precompute + edge scatter (fused) --------------
#define NPRE_BLKS 196            // ceil(50000/256)
#define SCAT_BLKS ((N_EDGES + 255) / 256)
__global__ void __launch_bounds__(256) pre_scatter_kernel(const float* __restrict__ x,
                                                          const int* __restrict__ ei) {
    int b = blockIdx.x;
    int tid = threadIdx.x;
    if (b >= 3 * NPRE_BLKS) {
        int e = (b - 3 * NPRE_BLKS) * 256 + tid;
        if (e < N_EDGES) {
            int r = __ldg(ei + e);
            int c = __ldg(ei + N_EDGES + e);
            int idx = atomicAdd(&g_cursor[c], 1);
            if (idx < SLOT) g_slot[c * SLOT + idx] = make_int2(r, e);
        }
        return;
    }
    __shared__ __align__(16) float sx[256 * 16];
    int arr = b / NPRE_BLKS;
    int n0 = (b % NPRE_BLKS) * 256;
    {
        const float4* xp = (const float4*)(x + (size_t)n0 * 16);
        int maxv = (N_NODES - n0) * 4;
        if (maxv > 1024) maxv = 1024;
        float4* sp = (float4*)sx;
        for (int i = tid; i < maxv; i += 256) sp[i] = __ldg(xp + i);
    }
    int c4 = (tid & 31) * 4;
    const float* W = (arr == 0) ? g_A : (arr == 1) ? g_B : g_C;
    u64 wlo[16], whi[16];
#pragma unroll
    for (int i = 0; i < 16; i++) {
        float4 w = *(const float4*)&W[i * 128 + c4];
        wlo[i] = pk2(w.x, w.y);
        whi[i] = pk2(w.z, w.w);
    }
    u64 blo = 0, bhi = 0;
    if (arr == 2) {
        float4 bias = *(const float4*)&g_bu2[c4];
        blo = pk2(bias.x, bias.y);
        bhi = pk2(bias.z, bias.w);
    } else {
        blo = pk2(0.f, 0.f);
        bhi = blo;
    }
    float* dst = (arr == 0) ? g_ar : (arr == 1) ? g_ac : g_au;
    __syncthreads();
    int wp = tid >> 5;  // 0..7
    for (int s = 0; s < 32; s++) {
        int ln = wp + 8 * s;
        int node = n0 + ln;
        if (node >= N_NODES) break;
        u64 alo = blo, ahi = bhi;
#pragma unroll
        for (int i = 0; i < 16; i++) {
            float xv = sx[ln * 16 + i];
            u64 xd = pk2(xv, xv);
            alo = fma2(xd, wlo[i], alo);
            ahi = fma2(xd, whi[i], ahi);
        }
        float4 acc;
        upk2(acc.x, acc.y, alo);
        upk2(acc.z, acc.w, ahi);
        *(float4*)&dst[(size_t)node * 128 + c4] = acc;
    }
}

// ---------------- kernel 3: per-node message aggregation (warp/node) -----------
__global__ void __launch_bounds__(256) agg_kernel(const float* __restrict__ ea) {
    int tid = threadIdx.x;
    int warp = tid >> 5, lane = tid & 31;
    int n = blockIdx.x * 8 + warp;
    if (n >= N_NODES) return;
    int c4 = lane * 4;
    u64 wlo[8], whi[8];
#pragma unroll
    for (int i = 0; i < 8; i++) {
        float4 w = *(const float4*)&g_We2[i * 128 + c4];
        wlo[i] = pk2(w.x, w.y);
        whi[i] = pk2(w.z, w.w);
    }
    float4 basev = *(const float4*)&g_ac[(size_t)n * 128 + c4];
    float4 bm4 = *(const float4*)&g_bmsg[c4];
    u64 base_lo = pk2(basev.x + bm4.x, basev.y + bm4.y);
    u64 base_hi = pk2(basev.z + bm4.z, basev.w + bm4.w);

    int truedeg = g_cursor[n];
    int deg = truedeg < SLOT ? truedeg : SLOT;
    float4 acc = make_float4(0.f, 0.f, 0.f, 0.f);

    for (int b0 = 0; b0 < deg; b0 += 32) {
        int cnt = deg - b0;
        if (cnt > 32) cnt = 32;
        int2 se = make_int2(0, 0);
        if (lane < cnt) se = __ldg(&g_slot[(size_t)n * SLOT + b0 + lane]);
#pragma unroll 4
        for (int j = 0; j < cnt; j++) {
            int r = __shfl_sync(0xffffffffu, se.x, j);
            int e = __shfl_sync(0xffffffffu, se.y, j);
            const float4* ep = (const float4*)(ea + (size_t)e * 8);
            float4 e0 = __ldg(ep), e1 = __ldg(ep + 1);
            float4 ar = __ldg((const float4*)&g_ar[(size_t)r * 128 + c4]);
            u64 mlo = add2(base_lo, pk2(ar.x, ar.y));
            u64 mhi = add2(base_hi, pk2(ar.z, ar.w));
            u64 ed;
            ed = pk2(e0.x, e0.x); mlo = fma2(ed, wlo[0], mlo); mhi = fma2(ed, whi[0], mhi);
            ed = pk2(e0.y, e0.y); mlo = fma2(ed, wlo[1], mlo); mhi = fma2(ed, whi[1], mhi);
            ed = pk2(e0.z, e0.z); mlo = fma2(ed, wlo[2], mlo); mhi = fma2(ed, whi[2], mhi);
            ed = pk2(e0.w, e0.w); mlo = fma2(ed, wlo[3], mlo); mhi = fma2(ed, whi[3], mhi);
            ed = pk2(e1.x, e1.x); mlo = fma2(ed, wlo[4], mlo); mhi = fma2(ed, whi[4], mhi);
            ed = pk2(e1.y, e1.y); mlo = fma2(ed, wlo[5], mlo); mhi = fma2(ed, whi[5], mhi);
            ed = pk2(e1.z, e1.z); mlo = fma2(ed, wlo[6], mlo); mhi = fma2(ed, whi[6], mhi);
            ed = pk2(e1.w, e1.w); mlo = fma2(ed, wlo[7], mlo); mhi = fma2(ed, whi[7], mhi);
            float mx, my, mz, mw;
            upk2(mx, my, mlo);
            upk2(mz, mw, mhi);
            acc.x += fmaxf(mx, 0.f);
            acc.y += fmaxf(my, 0.f);
            acc.z += fmaxf(mz, 0.f);
            acc.w += fmaxf(mw, 0.f);
        }
    }
    float inv = 1.f / fmaxf((float)truedeg, 1.f);
    acc.x *= inv; acc.y *= inv; acc.z *= inv; acc.w *= inv;
    *(float4*)&g_agg[(size_t)n * 128 + c4] = acc;
}

// ---------------- kernel 4: persistent tensor-core node update, reg-pipelined ---
// Wu2 tf32 staged once/block. agg tiles software-pipelined through registers:
// next tile's 32 floats/thread prefetched (8x float4, coalesced) during the
// current tile's MMA loop; tile-boundary staging is reg->smem only.
#define SA_STRIDE 132
#define SB_STRIDE 136
#define SMEM_PERS ((64 * SA_STRIDE + 128 * SB_STRIDE) * 4)   // 103424 B
#define NTILES ((N_NODES + 63) / 64)                         // 782
#define PERS_BLKS 296

__global__ void __launch_bounds__(256) node_upd_tc(const int* __restrict__ batch,
                                                   const float* __restrict__ Wu) {
    extern __shared__ u32 su[];
    float* sA = (float*)su;              // 64 * 132 fp32
    u32* sB = su + 64 * SA_STRIDE;       // 128 * 136 tf32
    int tid = threadIdx.x;

    // stage full Wu2 as tf32 once
    const float* Wu2 = Wu + 128 * 128;
    for (int i = tid; i < 128 * 128; i += 256) {
        int kl = i >> 7, nn = i & 127;
        sB[kl * SB_STRIDE + nn] = to_tf32(__ldg(Wu2 + i));
    }

    int lane = tid & 31;
    int grp = lane >> 2, tig = lane & 3;
    int warp = tid >> 5;
    int mBase = (warp & 3) * 16;
    int nHalf = warp >> 2;
    int nBase = nHalf * 64;

    // prefetch registers: thread covers float4 slots i4 = j*256+tid
    float4 pf[8];
    int pf_ln[8], pf_k[8];
#pragma unroll
    for (int j = 0; j < 8; j++) {
        int i4 = j * 256 + tid;
        pf_ln[j] = i4 >> 5;
        pf_k[j] = (i4 & 31) * 4;
    }

    int tile = blockIdx.x;
    if (tile < NTILES) {
        int n0 = tile * 64;
#pragma unroll
        for (int j = 0; j < 8; j++) {
            int node = n0 + pf_ln[j];
            if (node >= N_NODES) node = 0;
            pf[j] = __ldg((const float4*)&g_agg[(size_t)node * 128 + pf_k[j]]);
        }
    }

    for (; tile < NTILES; tile += PERS_BLKS) {
        int n0 = tile * 64;
        __syncthreads();   // sA free from previous tile's MMA reads
        // reg -> smem staging (no memory wait here)
#pragma unroll
        for (int j = 0; j < 8; j++) {
            float* d = &sA[pf_ln[j] * SA_STRIDE + pf_k[j]];
            d[0] = pf[j].x; d[1] = pf[j].y; d[2] = pf[j].z; d[3] = pf[j].w;
        }

        // accumulator init from g_au (16 independent float2 loads, overlaps staging)
        int node0 = n0 + mBase + grp;
        int node1 = node0 + 8;
        int s0 = (node0 < N_NODES) ? node0 : 0;
        int s1 = (node1 < N_NODES) ? node1 : 0;
        float acc[8][4];
#pragma unroll
        for (int t = 0; t < 8; t++) {
            int col = nBase + t * 8 + 2 * tig;
            float2 a0 = *(const float2*)&g_au[(size_t)s0 * 128 + col];
            float2 a1 = *(const float2*)&g_au[(size_t)s1 * 128 + col];
            acc[t][0] = a0.x; acc[t][1] = a0.y;
            acc[t][2] = a1.x; acc[t][3] = a1.y;
        }

        // issue next tile's agg prefetch (consumed after next barrier)
        int nxt = tile + PERS_BLKS;
        if (nxt < NTILES) {
            int m0 = nxt * 64;
#pragma unroll
            for (int j = 0; j < 8; j++) {
                int node = m0 + pf_ln[j];
                if (node >= N_NODES) node = 0;
                pf[j] = __ldg((const float4*)&g_agg[(size_t)node * 128 + pf_k[j]]);
            }
        }
        __syncthreads();   // sA ready

#pragma unroll
        for (int kk = 0; kk < 128; kk += 8) {
            u32 a0 = to_tf32(sA[(mBase + grp) * SA_STRIDE + kk + tig]);
            u32 a1 = to_tf32(sA[(mBase + grp + 8) * SA_STRIDE + kk + tig]);
            u32 a2 = to_tf32(sA[(mBase + grp) * SA_STRIDE + kk + tig + 4]);
            u32 a3 = to_tf32(sA[(mBase + grp + 8) * SA_STRIDE + kk + tig + 4]);
#pragma unroll
            for (int t = 0; t < 8; t++) {
                int nb = nBase + t * 8;
                u32 b0 = sB[(kk + tig) * SB_STRIDE + nb + grp];
                u32 b1 = sB[(kk + tig + 4) * SB_STRIDE + nb + grp];
                asm volatile(
                    "mma.sync.aligned.m16n8k8.row.col.f32.tf32.tf32.f32 "
                    "{%0,%1,%2,%3}, {%4,%5,%6,%7}, {%8,%9}, {%0,%1,%2,%3};"
                    : "+f"(acc[t][0]), "+f"(acc[t][1]), "+f"(acc[t][2]), "+f"(acc[t][3])
                    : "r"(a0), "r"(a1), "r"(a2), "r"(a3), "r"(b0), "r"(b1));
            }
        }

        // epilogue: relu + graph pooling
        int b0v = (node0 < N_NODES) ? __ldg(batch + node0) : 0;
        int b1v = (node1 < N_NODES) ? __ldg(batch + node1) : 0;
#pragma unroll
        for (int t = 0; t < 8; t++) {
            int col = nBase + t * 8 + 2 * tig;
            if (node0 < N_NODES) {
                float vx = fmaxf(acc[t][0], 0.f), vy = fmaxf(acc[t][1], 0.f);
                float* dst = &g_gsum[b0v * 128 + col];
                asm volatile("red.global.add.v2.f32 [%0], {%1,%2};"
                             :: "l"(dst), "f"(vx), "f"(vy) : "memory");
            }
            if (node1 < N_NODES) {
                float vx = fmaxf(acc[t][2], 0.f), vy = fmaxf(acc[t][3], 0.f);
                float* dst = &g_gsum[b1v * 128 + col];
                asm volatile("red.global.add.v2.f32 [%0], {%1,%2};"
                             :: "l"(dst), "f"(vx), "f"(vy) : "memory");
            }
        }
        if (nHalf == 0 && tig == 0) {
            if (node0 < N_NODES) atomicAdd(&g_gcnt[b0v], 1.0f);
            if (node1 < N_NODES) atomicAdd(&g_gcnt[b1v], 1.0f);
        }
    }
}

// ---------------- kernel 5: readout MLP -----------------------------------------
__global__ void __launch_bounds__(128) final_kernel(const float* __restrict__ Wr1,
                                                    const float* __restrict__ br1,
                                                    const float* __restrict__ Wr2,
                                                    const float* __restrict__ br2,
                                                    float* __restrict__ out) {
    __shared__ float gvec[128];
    __shared__ float red[128];
    int g = blockIdx.x, j = threadIdx.x;
    float s = 1.f / fmaxf(g_gcnt[g], 1.f);
    gvec[j] = g_gsum[g * 128 + j] * s;
    __syncthreads();
    float r = br1[j];
    for (int k = 0; k < 128; k++) r += gvec[k] * __ldg(Wr1 + k * 128 + j);
    r = fmaxf(r, 0.f);
    red[j] = r * __ldg(Wr2 + j);
    __syncthreads();
    for (int s2 = 64; s2 > 0; s2 >>= 1) {
        if (j < s2) red[j] += red[j + s2];
        __syncthreads();
    }
    if (j == 0) out[g] = red[0] + br2[0];
}

// ---------------- launch ---------------------------------------------------------
extern "C" void kernel_launch(void* const* d_in, const int* in_sizes, int n_in,
                              void* d_out, int out_size) {
    const float* x = (const float*)d_in[0];
    const float* ea = (const float*)d_in[1];
    const int* ei = (const int*)d_in[2];
    const int* batch = (const int*)d_in[3];
    const float* Wn = (const float*)d_in[4];
    const float* bn = (const float*)d_in[5];
    const float* We = (const float*)d_in[6];
    const float* be = (const float*)d_in[7];
    const float* Wm = (const float*)d_in[8];
    const float* bm = (const float*)d_in[9];
    const float* Wu = (const float*)d_in[10];
    const float* bu = (const float*)d_in[11];
    const float* Wr1 = (const float*)d_in[12];
    const float* br1 = (const float*)d_in[13];
    const float* Wr2 = (const float*)d_in[14];
    const float* br2 = (const float*)d_in[15];
    float* out = (float*)d_out;

    static int smem_set = 0;
    if (!smem_set) {
        cudaFuncSetAttribute(node_upd_tc, cudaFuncAttributeMaxDynamicSharedMemorySize, SMEM_PERS);
        smem_set = 1;
    }

    init_kernel<<<25 + 256, 256>>>(Wn, bn, We, be, Wm, bm, Wu, bu);
    pre_scatter_kernel<<<3 * NPRE_BLKS + SCAT_BLKS, 256>>>(x, ei);
    agg_kernel<<<(N_NODES + 7) / 8, 256>>>(ea);
    node_upd_tc<<<PERS_BLKS, 256, SMEM_PERS>>>(batch, Wu);
    final_kernel<<<NUM_GRAPHS, 128>>>(Wr1, br1, Wr2, br2, out);
}

// round 15
// speedup vs baseline: 1.2552x; 1.2552x over previous
#include <cuda_runtime.h>
#include <cuda_bf16.h>

#define N_NODES 50000
#define N_EDGES 500000
#define HID 128
#define NUM_GRAPHS 64
#define SLOT 64

typedef unsigned long long u64;
typedef unsigned int u32;

__device__ __forceinline__ u64 pk2(float lo, float hi) {
    u64 r; asm("mov.b64 %0, {%1,%2};" : "=l"(r) : "f"(lo), "f"(hi)); return r;
}
__device__ __forceinline__ void upk2(float& lo, float& hi, u64 v) {
    asm("mov.b64 {%0,%1}, %2;" : "=f"(lo), "=f"(hi) : "l"(v));
}
__device__ __forceinline__ u64 fma2(u64 a, u64 b, u64 c) {
    u64 d; asm("fma.rn.f32x2 %0, %1, %2, %3;" : "=l"(d) : "l"(a), "l"(b), "l"(c)); return d;
}
__device__ __forceinline__ u64 add2(u64 a, u64 b) {
    u64 d; asm("add.rn.f32x2 %0, %1, %2;" : "=l"(d) : "l"(a), "l"(b)); return d;
}
__device__ __forceinline__ u32 to_tf32(float f) {
    u32 r; asm("cvt.rna.tf32.f32 %0, %1;" : "=r"(r) : "f"(f)); return r;
}

// ---------------- scratch (device globals) ------------------------------------
__device__ __align__(16) float g_ar[N_NODES * HID];
__device__ __align__(16) float g_ac[N_NODES * HID];
__device__ __align__(16) float g_au[N_NODES * HID];
__device__ __align__(16) float g_agg[N_NODES * HID];
__device__ __align__(16) float g_gsum[NUM_GRAPHS * HID];
__device__ float g_gcnt[NUM_GRAPHS];

__device__ int g_cursor[N_NODES];
__device__ __align__(8) int2 g_slot[N_NODES * SLOT];

// folded weights
__device__ __align__(16) float g_A[16 * HID];
__device__ __align__(16) float g_B[16 * HID];
__device__ __align__(16) float g_C[16 * HID];
__device__ __align__(16) float g_We2[8 * HID];
__device__ float g_bmsg[HID];
__device__ float g_bu2[HID];

// ---------------- kernel 1: zero + fold (fused) --------------------------------
__global__ void __launch_bounds__(256) init_kernel(
        const float* __restrict__ Wn, const float* __restrict__ bn,
        const float* __restrict__ We, const float* __restrict__ be,
        const float* __restrict__ Wm, const float* __restrict__ bm,
        const float* __restrict__ Wu, const float* __restrict__ bu) {
    int b = blockIdx.x;
    int tid = threadIdx.x;
    if (b >= 25) {
        int nz = gridDim.x - 25;
        int i = (b - 25) * 256 + tid;
        int stride = nz * 256;
        for (int k = i; k < N_NODES; k += stride) g_cursor[k] = 0;
        for (int k = i; k < NUM_GRAPHS * HID; k += stride) g_gsum[k] = 0.f;
        for (int k = i; k < NUM_GRAPHS; k += stride) g_gcnt[k] = 0.f;
        return;
    }
    if (tid >= 128) return;
    int j = tid;
    if (b < 16) {
        int i = b;
        float sa = 0.f, sb = 0.f, sc = 0.f;
        for (int k = 0; k < 128; k++) {
            float w = __ldg(Wn + i * 128 + k);
            sa += w * __ldg(Wm + k * 128 + j);
            sb += w * __ldg(Wm + (128 + k) * 128 + j);
            sc += w * __ldg(Wu + k * 128 + j);
        }
        g_A[i * 128 + j] = sa;
        g_B[i * 128 + j] = sb;
        g_C[i * 128 + j] = sc;
    } else if (b < 24) {
        int i = b - 16;
        float s = 0.f;
        for (int k = 0; k < 128; k++)
            s += __ldg(We + i * 128 + k) * __ldg(Wm + (256 + k) * 128 + j);
        g_We2[i * 128 + j] = s;
    } else {
        float bmsg = bm[j];
        float bu2 = bu[j];
        for (int k = 0; k < 128; k++) {
            bmsg += bn[k] * (__ldg(Wm + k * 128 + j) + __ldg(Wm + (128 + k) * 128 + j));
            bmsg += be[k] * __ldg(Wm + (256 + k) * 128 + j);
            bu2 += bn[k] * __ldg(Wu + k * 128 + j);
        }
        g_bmsg[j] = bmsg;
        g_bu2[j] = bu2;
    }
}

// ---------------- kernel 2: node precompute + edge scatter (fused) --------------
#define NPRE_BLKS 196            // ceil(50000/256)
#define SCAT_BLKS ((N_EDGES + 255) / 256)
__global__ void __launch_bounds__(256) pre_scatter_kernel(const float* __restrict__ x,
                                                          const int* __restrict__ ei) {
    int b = blockIdx.x;
    int tid = threadIdx.x;
    if (b >= 3 * NPRE_BLKS) {
        int e = (b - 3 * NPRE_BLKS) * 256 + tid;
        if (e < N_EDGES) {
            int r = __ldg(ei + e);
            int c = __ldg(ei + N_EDGES + e);
            int idx = atomicAdd(&g_cursor[c], 1);
            if (idx < SLOT) g_slot[c * SLOT + idx] = make_int2(r, e);
        }
        return;
    }
    __shared__ __align__(16) float sx[256 * 16];
    int arr = b / NPRE_BLKS;
    int n0 = (b % NPRE_BLKS) * 256;
    {
        const float4* xp = (const float4*)(x + (size_t)n0 * 16);
        int maxv = (N_NODES - n0) * 4;
        if (maxv > 1024) maxv = 1024;
        float4* sp = (float4*)sx;
        for (int i = tid; i < maxv; i += 256) sp[i] = __ldg(xp + i);
    }
    int c4 = (tid & 31) * 4;
    const float* W = (arr == 0) ? g_A : (arr == 1) ? g_B : g_C;
    u64 wlo[16], whi[16];
#pragma unroll
    for (int i = 0; i < 16; i++) {
        float4 w = *(const float4*)&W[i * 128 + c4];
        wlo[i] = pk2(w.x, w.y);
        whi[i] = pk2(w.z, w.w);
    }
    u64 blo = 0, bhi = 0;
    if (arr == 2) {
        float4 bias = *(const float4*)&g_bu2[c4];
        blo = pk2(bias.x, bias.y);
        bhi = pk2(bias.z, bias.w);
    } else {
        blo = pk2(0.f, 0.f);
        bhi = blo;
    }
    float* dst = (arr == 0) ? g_ar : (arr == 1) ? g_ac : g_au;
    __syncthreads();
    int wp = tid >> 5;  // 0..7
    for (int s = 0; s < 32; s++) {
        int ln = wp + 8 * s;
        int node = n0 + ln;
        if (node >= N_NODES) break;
        u64 alo = blo, ahi = bhi;
#pragma unroll
        for (int i = 0; i < 16; i++) {
            float xv = sx[ln * 16 + i];
            u64 xd = pk2(xv, xv);
            alo = fma2(xd, wlo[i], alo);
            ahi = fma2(xd, whi[i], ahi);
        }
        float4 acc;
        upk2(acc.x, acc.y, alo);
        upk2(acc.z, acc.w, ahi);
        *(float4*)&dst[(size_t)node * 128 + c4] = acc;
    }
}

// ---------------- kernel 3: per-node message aggregation (warp/node) -----------
__global__ void __launch_bounds__(256) agg_kernel(const float* __restrict__ ea) {
    int tid = threadIdx.x;
    int warp = tid >> 5, lane = tid & 31;
    int n = blockIdx.x * 8 + warp;
    if (n >= N_NODES) return;
    int c4 = lane * 4;
    u64 wlo[8], whi[8];
#pragma unroll
    for (int i = 0; i < 8; i++) {
        float4 w = *(const float4*)&g_We2[i * 128 + c4];
        wlo[i] = pk2(w.x, w.y);
        whi[i] = pk2(w.z, w.w);
    }
    float4 basev = *(const float4*)&g_ac[(size_t)n * 128 + c4];
    float4 bm4 = *(const float4*)&g_bmsg[c4];
    u64 base_lo = pk2(basev.x + bm4.x, basev.y + bm4.y);
    u64 base_hi = pk2(basev.z + bm4.z, basev.w + bm4.w);

    int truedeg = g_cursor[n];
    int deg = truedeg < SLOT ? truedeg : SLOT;
    float4 acc = make_float4(0.f, 0.f, 0.f, 0.f);

    for (int b0 = 0; b0 < deg; b0 += 32) {
        int cnt = deg - b0;
        if (cnt > 32) cnt = 32;
        int2 se = make_int2(0, 0);
        if (lane < cnt) se = __ldg(&g_slot[(size_t)n * SLOT + b0 + lane]);
#pragma unroll 4
        for (int j = 0; j < cnt; j++) {
            int r = __shfl_sync(0xffffffffu, se.x, j);
            int e = __shfl_sync(0xffffffffu, se.y, j);
            const float4* ep = (const float4*)(ea + (size_t)e * 8);
            float4 e0 = __ldg(ep), e1 = __ldg(ep + 1);
            float4 ar = __ldg((const float4*)&g_ar[(size_t)r * 128 + c4]);
            u64 mlo = add2(base_lo, pk2(ar.x, ar.y));
            u64 mhi = add2(base_hi, pk2(ar.z, ar.w));
            u64 ed;
            ed = pk2(e0.x, e0.x); mlo = fma2(ed, wlo[0], mlo); mhi = fma2(ed, whi[0], mhi);
            ed = pk2(e0.y, e0.y); mlo = fma2(ed, wlo[1], mlo); mhi = fma2(ed, whi[1], mhi);
            ed = pk2(e0.z, e0.z); mlo = fma2(ed, wlo[2], mlo); mhi = fma2(ed, whi[2], mhi);
            ed = pk2(e0.w, e0.w); mlo = fma2(ed, wlo[3], mlo); mhi = fma2(ed, whi[3], mhi);
            ed = pk2(e1.x, e1.x); mlo = fma2(ed, wlo[4], mlo); mhi = fma2(ed, whi[4], mhi);
            ed = pk2(e1.y, e1.y); mlo = fma2(ed, wlo[5], mlo); mhi = fma2(ed, whi[5], mhi);
            ed = pk2(e1.z, e1.z); mlo = fma2(ed, wlo[6], mlo); mhi = fma2(ed, whi[6], mhi);
            ed = pk2(e1.w, e1.w); mlo = fma2(ed, wlo[7], mlo); mhi = fma2(ed, whi[7], mhi);
            float mx, my, mz, mw;
            upk2(mx, my, mlo);
            upk2(mz, mw, mhi);
            acc.x += fmaxf(mx, 0.f);
            acc.y += fmaxf(my, 0.f);
            acc.z += fmaxf(mz, 0.f);
            acc.w += fmaxf(mw, 0.f);
        }
    }
    float inv = 1.f / fmaxf((float)truedeg, 1.f);
    acc.x *= inv; acc.y *= inv; acc.z *= inv; acc.w *= inv;
    *(float4*)&g_agg[(size_t)n * 128 + c4] = acc;
}

// ---------------- kernel 4: persistent tensor-core node update ------------------
// 512 threads (16 warps): warp -> mTile = w&3 (16 nodes), nQ = w>>2 (32 cols).
// Wu2 tf32 staged once/block; agg tiles pipelined via registers. Pooling uses
// the SORTED batch: single-graph full tiles reduce via shfl butterfly (16x
// fewer REDs); boundary/partial tiles take the per-node path.
#define SA_STRIDE 132
#define SB_STRIDE 136
#define SMEM_PERS ((64 * SA_STRIDE + 128 * SB_STRIDE) * 4)   // 103424 B
#define NTILES ((N_NODES + 63) / 64)                         // 782
#define PERS_BLKS 296

__global__ void __launch_bounds__(512) node_upd_tc(const int* __restrict__ batch,
                                                   const float* __restrict__ Wu) {
    extern __shared__ u32 su[];
    float* sA = (float*)su;              // 64 * 132 fp32
    u32* sB = su + 64 * SA_STRIDE;       // 128 * 136 tf32
    int tid = threadIdx.x;

    // stage full Wu2 as tf32 once
    const float* Wu2 = Wu + 128 * 128;
    for (int i = tid; i < 128 * 128; i += 512) {
        int kl = i >> 7, nn = i & 127;
        sB[kl * SB_STRIDE + nn] = to_tf32(__ldg(Wu2 + i));
    }

    int lane = tid & 31;
    int grp = lane >> 2, tig = lane & 3;
    int warp = tid >> 5;                 // 0..15
    int mBase = (warp & 3) * 16;
    int nQ = warp >> 2;                  // 0..3
    int nBase = nQ * 32;

    // prefetch registers: thread covers float4 slots i4 = j*512+tid (2048 total)
    float4 pf[4];
    int pf_ln[4], pf_k[4];
#pragma unroll
    for (int j = 0; j < 4; j++) {
        int i4 = j * 512 + tid;
        pf_ln[j] = i4 >> 5;
        pf_k[j] = (i4 & 31) * 4;
    }

    int tile = blockIdx.x;
    if (tile < NTILES) {
        int n0 = tile * 64;
#pragma unroll
        for (int j = 0; j < 4; j++) {
            int node = n0 + pf_ln[j];
            if (node >= N_NODES) node = 0;
            pf[j] = __ldg((const float4*)&g_agg[(size_t)node * 128 + pf_k[j]]);
        }
    }

    for (; tile < NTILES; tile += PERS_BLKS) {
        int n0 = tile * 64;
        __syncthreads();   // sA free from previous tile's MMA reads
#pragma unroll
        for (int j = 0; j < 4; j++) {
            float* d = &sA[pf_ln[j] * SA_STRIDE + pf_k[j]];
            d[0] = pf[j].x; d[1] = pf[j].y; d[2] = pf[j].z; d[3] = pf[j].w;
        }

        int node0 = n0 + mBase + grp;
        int node1 = node0 + 8;
        int s0 = (node0 < N_NODES) ? node0 : 0;
        int s1 = (node1 < N_NODES) ? node1 : 0;
        float acc[4][4];
#pragma unroll
        for (int t = 0; t < 4; t++) {
            int col = nBase + t * 8 + 2 * tig;
            float2 a0 = *(const float2*)&g_au[(size_t)s0 * 128 + col];
            float2 a1 = *(const float2*)&g_au[(size_t)s1 * 128 + col];
            acc[t][0] = a0.x; acc[t][1] = a0.y;
            acc[t][2] = a1.x; acc[t][3] = a1.y;
        }

        // issue next tile's agg prefetch (consumed after next barrier)
        int nxt = tile + PERS_BLKS;
        if (nxt < NTILES) {
            int m0 = nxt * 64;
#pragma unroll
            for (int j = 0; j < 4; j++) {
                int node = m0 + pf_ln[j];
                if (node >= N_NODES) node = 0;
                pf[j] = __ldg((const float4*)&g_agg[(size_t)node * 128 + pf_k[j]]);
            }
        }
        __syncthreads();   // sA ready

#pragma unroll
        for (int kk = 0; kk < 128; kk += 8) {
            u32 a0 = to_tf32(sA[(mBase + grp) * SA_STRIDE + kk + tig]);
            u32 a1 = to_tf32(sA[(mBase + grp + 8) * SA_STRIDE + kk + tig]);
            u32 a2 = to_tf32(sA[(mBase + grp) * SA_STRIDE + kk + tig + 4]);
            u32 a3 = to_tf32(sA[(mBase + grp + 8) * SA_STRIDE + kk + tig + 4]);
#pragma unroll
            for (int t = 0; t < 4; t++) {
                int nb = nBase + t * 8;
                u32 b0 = sB[(kk + tig) * SB_STRIDE + nb + grp];
                u32 b1 = sB[(kk + tig + 4) * SB_STRIDE + nb + grp];
                asm volatile(
                    "mma.sync.aligned.m16n8k8.row.col.f32.tf32.tf32.f32 "
                    "{%0,%1,%2,%3}, {%4,%5,%6,%7}, {%8,%9}, {%0,%1,%2,%3};"
                    : "+f"(acc[t][0]), "+f"(acc[t][1]), "+f"(acc[t][2]), "+f"(acc[t][3])
                    : "r"(a0), "r"(a1), "r"(a2), "r"(a3), "r"(b0), "r"(b1));
            }
        }

        // relu (pre-pooling, matches reference)
#pragma unroll
        for (int t = 0; t < 4; t++) {
#pragma unroll
            for (int i = 0; i < 4; i++) acc[t][i] = fmaxf(acc[t][i], 0.f);
        }

        // pooling epilogue
        bool full = (n0 + 64 <= N_NODES);
        int gFirst = __ldg(batch + ((n0 < N_NODES) ? n0 : 0));
        bool uniform = full && (gFirst == __ldg(batch + n0 + 63));

        if (uniform) {
            // fast path: butterfly-reduce 16 nodes per warp in registers
#pragma unroll
            for (int t = 0; t < 4; t++) {
#pragma unroll
                for (int i = 0; i < 4; i++) {
                    acc[t][i] += __shfl_xor_sync(0xffffffffu, acc[t][i], 4);
                    acc[t][i] += __shfl_xor_sync(0xffffffffu, acc[t][i], 8);
                    acc[t][i] += __shfl_xor_sync(0xffffffffu, acc[t][i], 16);
                }
            }
            if (lane < 4) {   // grp==0, tig==lane
#pragma unroll
                for (int t = 0; t < 4; t++) {
                    int col = nBase + t * 8 + 2 * lane;
                    float vx = acc[t][0] + acc[t][2];
                    float vy = acc[t][1] + acc[t][3];
                    float* dst = &g_gsum[gFirst * 128 + col];
                    asm volatile("red.global.add.v2.f32 [%0], {%1,%2};"
                                 :: "l"(dst), "f"(vx), "f"(vy) : "memory");
                }
            }
            if (tid == 0) atomicAdd(&g_gcnt[gFirst], 64.0f);
        } else {
            // slow path: per-node REDs (boundary / partial tiles)
            int b0v = (node0 < N_NODES) ? __ldg(batch + node0) : 0;
            int b1v = (node1 < N_NODES) ? __ldg(batch + node1) : 0;
#pragma unroll
            for (int t = 0; t < 4; t++) {
                int col = nBase + t * 8 + 2 * tig;
                if (node0 < N_NODES) {
                    float* dst = &g_gsum[b0v * 128 + col];
                    asm volatile("red.global.add.v2.f32 [%0], {%1,%2};"
                                 :: "l"(dst), "f"(acc[t][0]), "f"(acc[t][1]) : "memory");
                }
                if (node1 < N_NODES) {
                    float* dst = &g_gsum[b1v * 128 + col];
                    asm volatile("red.global.add.v2.f32 [%0], {%1,%2};"
                                 :: "l"(dst), "f"(acc[t][2]), "f"(acc[t][3]) : "memory");
                }
            }
            if (nQ == 0 && tig == 0) {
                if (node0 < N_NODES) atomicAdd(&g_gcnt[b0v], 1.0f);
                if (node1 < N_NODES) atomicAdd(&g_gcnt[b1v], 1.0f);
            }
        }
    }
}

// ---------------- kernel 5: readout MLP -----------------------------------------
__global__ void __launch_bounds__(128) final_kernel(const float* __restrict__ Wr1,
                                                    const float* __restrict__ br1,
                                                    const float* __restrict__ Wr2,
                                                    const float* __restrict__ br2,
                                                    float* __restrict__ out) {
    __shared__ float gvec[128];
    __shared__ float red[128];
    int g = blockIdx.x, j = threadIdx.x;
    float s = 1.f / fmaxf(g_gcnt[g], 1.f);
    gvec[j] = g_gsum[g * 128 + j] * s;
    __syncthreads();
    float r = br1[j];
    for (int k = 0; k < 128; k++) r += gvec[k] * __ldg(Wr1 + k * 128 + j);
    r = fmaxf(r, 0.f);
    red[j] = r * __ldg(Wr2 + j);
    __syncthreads();
    for (int s2 = 64; s2 > 0; s2 >>= 1) {
        if (j < s2) red[j] += red[j + s2];
        __syncthreads();
    }
    if (j == 0) out[g] = red[0] + br2[0];
}

// ---------------- launch ---------------------------------------------------------
extern "C" void kernel_launch(void* const* d_in, const int* in_sizes, int n_in,
                              void* d_out, int out_size) {
    const float* x = (const float*)d_in[0];
    const float* ea = (const float*)d_in[1];
    const int* ei = (const int*)d_in[2];
    const int* batch = (const int*)d_in[3];
    const float* Wn = (const float*)d_in[4];
    const float* bn = (const float*)d_in[5];
    const float* We = (const float*)d_in[6];
    const float* be = (const float*)d_in[7];
    const float* Wm = (const float*)d_in[8];
    const float* bm = (const float*)d_in[9];
    const float* Wu = (const float*)d_in[10];
    const float* bu = (const float*)d_in[11];
    const float* Wr1 = (const float*)d_in[12];
    const float* br1 = (const float*)d_in[13];
    const float* Wr2 = (const float*)d_in[14];
    const float* br2 = (const float*)d_in[15];
    float* out = (float*)d_out;

    static int smem_set = 0;
    if (!smem_set) {
        cudaFuncSetAttribute(node_upd_tc, cudaFuncAttributeMaxDynamicSharedMemorySize, SMEM_PERS);
        smem_set = 1;
    }

    init_kernel<<<25 + 256, 256>>>(Wn, bn, We, be, Wm, bm, Wu, bu);
    pre_scatter_kernel<<<3 * NPRE_BLKS + SCAT_BLKS, 256>>>(x, ei);
    agg_kernel<<<(N_NODES + 7) / 8, 256>>>(ea);
    node_upd_tc<<<PERS_BLKS, 512, SMEM_PERS>>>(batch, Wu);
    final_kernel<<<NUM_GRAPHS, 128>>>(Wr1, br1, Wr2, br2, out);
}